// round 13
// baseline (speedup 1.0000x reference)
#include <cuda_runtime.h>
#include <cuda_fp16.h>
#include <cstdint>

// ---------------------------------------------------------------------------
// WindowAttention (reference semantics):
//   qkv = window_gather(x) @ w_qkv^T          [100352 x 768]
//   per token: A[h,e] = softmax_e(q_h . k_e / sqrt(32));  o_h = sum_e A[h,e] v_e
//   att layout per window: h*1568 + s*32 + d  (swapaxes(1,2) flatten)
//   out = att @ w_proj^T + b, window-scattered back to (32,56,56,256)
//
// fp16 m16n8k16 GEMMs, operands pre-converted fp16 k16-interleaved.
// B tile (128 x 256) RESIDENT in smem (one load); only A streams through a
// 4-stage cp.async ring. One __syncthreads per K-chunk.
// ---------------------------------------------------------------------------

#define M_TOK 100352
#define KDIM  256
#define QKV_N 768

__device__ __half g_qkv16[(size_t)M_TOK * QKV_N];          // fp16 plain
__device__ __half g_att16[(size_t)M_TOK * KDIM];           // fp16 interleaved
__device__ __half g_x16[(size_t)32 * 56 * 56 * 256];       // fp16 interleaved
__device__ __half g_wqkv16[(size_t)QKV_N * KDIM];
__device__ __half g_wproj16[(size_t)KDIM * KDIM];

__device__ __host__ __forceinline__ int kslot(int r) {
    return (r & 1) | (((r >> 3) & 1) << 1) | (((r >> 1) & 3) << 2);
}

__device__ __forceinline__ int row_offset(int n) {
    int w  = n / 49;
    int s  = n - w * 49;
    int b  = w >> 6;
    int wh = (w >> 3) & 7;
    int ww = w & 7;
    int r  = s / 7;
    int cc = s - r * 7;
    int hh = wh * 7 + r;
    int wc = ww * 7 + cc;
    return ((b * 56 + hh) * 56 + wc) * 256;
}

// ---------------- fp32 -> fp16 with k16 interleave -------------------------
__global__ void cvt16(const float* __restrict__ in, __half* __restrict__ out,
                      int ngroups)
{
    int i = blockIdx.x * blockDim.x + threadIdx.x;
    if (i >= ngroups) return;
    const float4* p = (const float4*)(in + (size_t)i * 16);
    float f[16];
    *(float4*)&f[0]  = p[0];
    *(float4*)&f[4]  = p[1];
    *(float4*)&f[8]  = p[2];
    *(float4*)&f[12] = p[3];
    __half t[16];
    #pragma unroll
    for (int r = 0; r < 16; r++) t[kslot(r)] = __float2half_rn(f[r]);
    uint4* o = (uint4*)(out + (size_t)i * 16);
    o[0] = *(uint4*)&t[0];
    o[1] = *(uint4*)&t[8];
}

// ---------------------------------------------------------------------------
// fp16 TC GEMM: C[M x NTOT] = A[M x 256] * B[NTOT x 256]^T
// 128x128 tile. B resident: 128 rows x 272 halves (544B rows, conflict-free).
// A: 4-stage ring of k32 chunks, rows 40 halves (80B, conflict-free).
// 8 warps x (64x32) warp tiles, frag pair = 1 LDS.64.
// ---------------------------------------------------------------------------
#define TBM 128
#define TBN 128
#define B_ROWB 544                      // bytes per resident B row (272 halves)
#define B_BYTES (128 * B_ROWB)          // 69632
#define A_ROWB 80                       // bytes per A chunk row (40 halves)
#define A_STGB (128 * A_ROWB)           // 10240
#define SMEMB (B_BYTES + 4 * A_STGB)    // 110592

__device__ __forceinline__ void cpa16(uint32_t s, const void* g) {
    asm volatile("cp.async.cg.shared.global [%0], [%1], 16;" :: "r"(s), "l"(g));
}
__device__ __forceinline__ uint2 lds64(uint32_t a) {
    uint2 r;
    asm volatile("ld.shared.v2.b32 {%0,%1}, [%2];" : "=r"(r.x), "=r"(r.y) : "r"(a));
    return r;
}
__device__ __forceinline__ void mma16816(float c[4], uint32_t a0, uint32_t a1,
                                         uint32_t a2, uint32_t a3,
                                         uint32_t b0, uint32_t b1) {
    asm volatile(
        "mma.sync.aligned.m16n8k16.row.col.f32.f16.f16.f32 "
        "{%0,%1,%2,%3}, {%4,%5,%6,%7}, {%8,%9}, {%0,%1,%2,%3};"
        : "+f"(c[0]), "+f"(c[1]), "+f"(c[2]), "+f"(c[3])
        : "r"(a0), "r"(a1), "r"(a2), "r"(a3), "r"(b0), "r"(b1));
}

template<int NTOT, bool GATHER_A, bool SCATTER_OUT, bool OUT_HALF>
__global__ __launch_bounds__(256, 2)
void gemm_h(const __half* __restrict__ A, const __half* __restrict__ B,
            const float* __restrict__ bias, void* __restrict__ CoutV)
{
    extern __shared__ __align__(16) __half sh[];
    const uint32_t sb  = (uint32_t)__cvta_generic_to_shared(sh);
    const uint32_t sbA = sb + B_BYTES;

    const int tid  = threadIdx.x;
    const int lane = tid & 31;
    const int warp = tid >> 5;
    const int wm = (warp & 1) * 64;
    const int wn = (warp >> 1) * 32;
    const int g  = lane >> 2;
    const int q  = lane & 3;

    const int m0 = blockIdx.y * TBM;
    const int n0 = blockIdx.x * TBN;

    // ---- loader geometry: 2 threads per row ----
    const int lrow = tid >> 1;
    const int lhlf = tid & 1;
    const long a_rowbase = GATHER_A ? (long)row_offset(m0 + lrow)
                                    : (long)(m0 + lrow) * KDIM;
    const long b_rowbase = (long)(n0 + lrow) * KDIM;

    // ---- resident B load: 128 rows x 512B; per thread 16 x 16B ----
    {
        const __half* bg = B + b_rowbase + lhlf * 128;
        const uint32_t bs = sb + (uint32_t)(lrow * B_ROWB + lhlf * 256);
        #pragma unroll
        for (int s = 0; s < 16; s++)
            cpa16(bs + s * 16, bg + s * 8);
        asm volatile("cp.async.commit_group;");
    }

    auto stageA = [&](int s, int kc) {
        const __half* ag = A + a_rowbase + kc + lhlf * 16;
        const uint32_t as = sbA + (uint32_t)(s * A_STGB + lrow * A_ROWB + lhlf * 32);
        cpa16(as,      ag);
        cpa16(as + 16, ag + 8);
        asm volatile("cp.async.commit_group;");
    };

    stageA(0, 0);
    stageA(1, 32);
    stageA(2, 64);

    // fragment base addresses
    const uint32_t aFrag = sbA + (uint32_t)((wm + g) * A_ROWB) + (uint32_t)(q * 8);
    const uint32_t bFrag = sb  + (uint32_t)((wn + g) * B_ROWB) + (uint32_t)(q * 8);

    float acc[4][4][4];
    #pragma unroll
    for (int i = 0; i < 4; i++)
        #pragma unroll
        for (int j = 0; j < 4; j++)
            #pragma unroll
            for (int c = 0; c < 4; c++) acc[i][j][c] = 0.f;

    const int NT = KDIM / 32;   // 8
    #pragma unroll 1
    for (int t = 0; t < NT; ++t) {
        asm volatile("cp.async.wait_group 2;");
        __syncthreads();
        if (t + 3 < NT) stageA((t + 3) & 3, (t + 3) * 32);

        const uint32_t ab = aFrag + (uint32_t)((t & 3) * A_STGB);
        #pragma unroll
        for (int kk = 0; kk < 2; kk++) {
            const uint32_t ako = (uint32_t)(kk * 32);
            const uint32_t bko = (uint32_t)((t * 2 + kk) * 32);
            uint32_t af[4][4];
            #pragma unroll
            for (int mt = 0; mt < 4; mt++) {
                uint2 lo = lds64(ab + (uint32_t)(mt * 16 * A_ROWB) + ako);
                uint2 hi = lds64(ab + (uint32_t)((mt * 16 + 8) * A_ROWB) + ako);
                af[mt][0] = lo.x; af[mt][1] = hi.x;
                af[mt][2] = lo.y; af[mt][3] = hi.y;
            }
            #pragma unroll
            for (int nt = 0; nt < 4; nt++) {
                uint2 b2 = lds64(bFrag + (uint32_t)(nt * 8 * B_ROWB) + bko);
                #pragma unroll
                for (int mt = 0; mt < 4; mt++)
                    mma16816(acc[mt][nt], af[mt][0], af[mt][1], af[mt][2],
                             af[mt][3], b2.x, b2.y);
            }
        }
    }

    // epilogue: c0,c1 = (row g, cols 2q,2q+1); c2,c3 = row g+8
    #pragma unroll
    for (int mt = 0; mt < 4; mt++) {
        #pragma unroll
        for (int ri = 0; ri < 2; ri++) {
            const int m = m0 + wm + mt * 16 + g + ri * 8;
            const long ob = SCATTER_OUT ? (long)row_offset(m) : (long)m * NTOT;
            #pragma unroll
            for (int nt = 0; nt < 4; nt++) {
                const int col = n0 + wn + nt * 8 + 2 * q;
                float vx = acc[mt][nt][ri * 2 + 0];
                float vy = acc[mt][nt][ri * 2 + 1];
                if (OUT_HALF) {
                    __half2 hv = __floats2half2_rn(vx, vy);
                    *(__half2*)((__half*)CoutV + ob + col) = hv;
                } else {
                    if (SCATTER_OUT) {
                        vx += bias[col];
                        vy += bias[col + 1];
                    }
                    float2 v; v.x = vx; v.y = vy;
                    *(float2*)((float*)CoutV + ob + col) = v;
                }
            }
        }
    }
}

// ---------------------------------------------------------------------------
// Per-token head-mixing attention: fp16 qkv in, fp32 compute,
// fp16 k16-interleaved att out.
// ---------------------------------------------------------------------------
#define ATT_TOK 14
#define ATT_THREADS (ATT_TOK * 8)

__global__ __launch_bounds__(ATT_THREADS)
void attn_kernel(const __half* __restrict__ qkv, __half* __restrict__ att)
{
    __shared__ float rows[ATT_TOK][776];

    const int tid  = threadIdx.x;
    const int tok0 = blockIdx.x * ATT_TOK;

    for (int i = tid; i < ATT_TOK * 96; i += ATT_THREADS) {
        int t = i / 96, c8 = (i - t * 96) * 8;
        uint4 u = *(const uint4*)(qkv + (size_t)(tok0 + t) * QKV_N + c8);
        const __half2* hp = (const __half2*)&u;
        float* rp = &rows[t][c8];
        #pragma unroll
        for (int j = 0; j < 4; j++) {
            float2 f = __half22float2(hp[j]);
            rp[2 * j]     = f.x;
            rp[2 * j + 1] = f.y;
        }
    }
    __syncthreads();

    const int t = tid >> 3;
    const int h = tid & 7;
    const float* row = rows[t];

    float qv[32];
    #pragma unroll
    for (int d = 0; d < 32; d++) qv[d] = row[h * 32 + d];

    const float scale = 0.17677669529663687f;
    float a[8];
    #pragma unroll
    for (int e = 0; e < 8; e++) {
        float acc = 0.f;
        #pragma unroll
        for (int d = 0; d < 32; d++) acc += qv[d] * row[256 + e * 32 + d];
        a[e] = acc * scale;
    }

    float mx = a[0];
    #pragma unroll
    for (int e = 1; e < 8; e++) mx = fmaxf(mx, a[e]);
    float sum = 0.f;
    #pragma unroll
    for (int e = 0; e < 8; e++) { a[e] = __expf(a[e] - mx); sum += a[e]; }
    float inv = 1.f / sum;
    #pragma unroll
    for (int e = 0; e < 8; e++) a[e] *= inv;

    float o[32];
    #pragma unroll
    for (int d = 0; d < 32; d++) {
        float acc = 0.f;
        #pragma unroll
        for (int e = 0; e < 8; e++) acc += a[e] * row[512 + e * 32 + d];
        o[d] = acc;
    }

    const int n = tok0 + t;
    const int w = n / 49;
    const int s = n - w * 49;
    __half* op = att + (size_t)w * 12544 + h * 1568 + s * 32;

    __half tmp[32];
    #pragma unroll
    for (int d = 0; d < 32; d++) {
        int g16 = d >> 4, r = d & 15;
        tmp[g16 * 16 + kslot(r)] = __float2half_rn(o[d]);
    }
    uint4* ov = (uint4*)op;
    ov[0] = *(uint4*)&tmp[0];
    ov[1] = *(uint4*)&tmp[8];
    ov[2] = *(uint4*)&tmp[16];
    ov[3] = *(uint4*)&tmp[24];
}

// ---------------------------------------------------------------------------
extern "C" void kernel_launch(void* const* d_in, const int* in_sizes, int n_in,
                              void* d_out, int out_size)
{
    (void)in_sizes; (void)n_in; (void)out_size;
    const float* x      = (const float*)d_in[0];
    const float* w_qkv  = (const float*)d_in[1];
    const float* w_proj = (const float*)d_in[2];
    const float* b_proj = (const float*)d_in[3];
    float* out = (float*)d_out;

    void *qkv_p, *att_p, *x16_p, *wq16_p, *wp16_p;
    cudaGetSymbolAddress(&qkv_p, g_qkv16);
    cudaGetSymbolAddress(&att_p, g_att16);
    cudaGetSymbolAddress(&x16_p, g_x16);
    cudaGetSymbolAddress(&wq16_p, g_wqkv16);
    cudaGetSymbolAddress(&wp16_p, g_wproj16);
    __half* qkv  = (__half*)qkv_p;
    __half* att  = (__half*)att_p;
    __half* x16  = (__half*)x16_p;
    __half* wq16 = (__half*)wq16_p;
    __half* wp16 = (__half*)wp16_p;

    static bool attr_done = false;
    if (!attr_done) {
        cudaFuncSetAttribute((const void*)gemm_h<QKV_N, true, false, true>,
                             cudaFuncAttributeMaxDynamicSharedMemorySize, SMEMB);
        cudaFuncSetAttribute((const void*)gemm_h<KDIM, false, true, false>,
                             cudaFuncAttributeMaxDynamicSharedMemorySize, SMEMB);
        attr_done = true;
    }

    // 0) fp32 -> fp16 (k16-interleaved) conversions
    {
        int ngx = 32 * 56 * 56 * 256 / 16;
        cvt16<<<(ngx + 255) / 256, 256>>>(x, x16, ngx);
        int ngq = QKV_N * KDIM / 16;
        cvt16<<<(ngq + 255) / 256, 256>>>(w_qkv, wq16, ngq);
        int ngp = KDIM * KDIM / 16;
        cvt16<<<(ngp + 255) / 256, 256>>>(w_proj, wp16, ngp);
    }
    // 1) QKV projection (gathered A), fp16 output
    {
        dim3 grid(QKV_N / TBN, M_TOK / TBM);   // (6, 784)
        gemm_h<QKV_N, true, false, true><<<grid, 256, SMEMB>>>(x16, wq16, nullptr, qkv);
    }
    // 2) attention (fp16 in, fp16 interleaved out)
    {
        attn_kernel<<<M_TOK / ATT_TOK, ATT_THREADS>>>(qkv, att);
    }
    // 3) output projection + bias + scatter (fp32 out)
    {
        dim3 grid(KDIM / TBN, M_TOK / TBM);    // (2, 784)
        gemm_h<KDIM, false, true, false><<<grid, 256, SMEMB>>>(att, wp16, b_proj, out);
    }
}

// round 14
// speedup vs baseline: 1.2224x; 1.2224x over previous
#include <cuda_runtime.h>
#include <cuda_fp16.h>
#include <cstdint>

// ---------------------------------------------------------------------------
// WindowAttention (reference semantics):
//   qkv = window_gather(x) @ w_qkv^T          [100352 x 768]
//   per token: A[h,e] = softmax_e(q_h . k_e / sqrt(32));  o_h = sum_e A[h,e] v_e
//   att layout per window: h*1568 + s*32 + d  (swapaxes(1,2) flatten)
//   out = att @ w_proj^T + b, window-scattered back to (32,56,56,256)
//
// fp16 m16n8k16 GEMMs (R12 structure: 4-stage cp.async ring, pad-48 rows,
// k16-interleaved operands, frag pair = 1 LDS.64). qkv intermediate fp16.
// Attention: fp16-resident smem (half2), fp32 compute.
// ---------------------------------------------------------------------------

#define M_TOK 100352
#define KDIM  256
#define QKV_N 768

__device__ __half g_qkv16[(size_t)M_TOK * QKV_N];          // fp16 plain
__device__ __half g_att16[(size_t)M_TOK * KDIM];           // fp16 interleaved
__device__ __half g_x16[(size_t)32 * 56 * 56 * 256];       // fp16 interleaved
__device__ __half g_wqkv16[(size_t)QKV_N * KDIM];
__device__ __half g_wproj16[(size_t)KDIM * KDIM];

__device__ __host__ __forceinline__ int kslot(int r) {
    return (r & 1) | (((r >> 3) & 1) << 1) | (((r >> 1) & 3) << 2);
}

__device__ __forceinline__ int row_offset(int n) {
    int w  = n / 49;
    int s  = n - w * 49;
    int b  = w >> 6;
    int wh = (w >> 3) & 7;
    int ww = w & 7;
    int r  = s / 7;
    int cc = s - r * 7;
    int hh = wh * 7 + r;
    int wc = ww * 7 + cc;
    return ((b * 56 + hh) * 56 + wc) * 256;
}

// ---------------- fp32 -> fp16 with k16 interleave -------------------------
__global__ void cvt16(const float* __restrict__ in, __half* __restrict__ out,
                      int ngroups)
{
    int i = blockIdx.x * blockDim.x + threadIdx.x;
    if (i >= ngroups) return;
    const float4* p = (const float4*)(in + (size_t)i * 16);
    float f[16];
    *(float4*)&f[0]  = p[0];
    *(float4*)&f[4]  = p[1];
    *(float4*)&f[8]  = p[2];
    *(float4*)&f[12] = p[3];
    __half t[16];
    #pragma unroll
    for (int r = 0; r < 16; r++) t[kslot(r)] = __float2half_rn(f[r]);
    uint4* o = (uint4*)(out + (size_t)i * 16);
    o[0] = *(uint4*)&t[0];
    o[1] = *(uint4*)&t[8];
}

// ---------------------------------------------------------------------------
// fp16 TC GEMM (R12 structure): C[M x NTOT] = A[M x 256] * B[NTOT x 256]^T
// ---------------------------------------------------------------------------
#define TBM 128
#define TBN 128
#define PADH 48                        // halves per chunk-row (96 B)
#define STG_H (128 * PADH)
#define STG_B (2 * STG_H * 2)          // 24576
#define SMEMB (4 * STG_B)              // 98304

__device__ __forceinline__ void cpa16(uint32_t s, const void* g) {
    asm volatile("cp.async.cg.shared.global [%0], [%1], 16;" :: "r"(s), "l"(g));
}
__device__ __forceinline__ uint2 lds64(uint32_t a) {
    uint2 r;
    asm volatile("ld.shared.v2.b32 {%0,%1}, [%2];" : "=r"(r.x), "=r"(r.y) : "r"(a));
    return r;
}
__device__ __forceinline__ void mma16816(float c[4], uint32_t a0, uint32_t a1,
                                         uint32_t a2, uint32_t a3,
                                         uint32_t b0, uint32_t b1) {
    asm volatile(
        "mma.sync.aligned.m16n8k16.row.col.f32.f16.f16.f32 "
        "{%0,%1,%2,%3}, {%4,%5,%6,%7}, {%8,%9}, {%0,%1,%2,%3};"
        : "+f"(c[0]), "+f"(c[1]), "+f"(c[2]), "+f"(c[3])
        : "r"(a0), "r"(a1), "r"(a2), "r"(a3), "r"(b0), "r"(b1));
}

template<int NTOT, bool GATHER_A, bool SCATTER_OUT, bool OUT_HALF>
__global__ __launch_bounds__(256, 2)
void gemm_h(const __half* __restrict__ A, const __half* __restrict__ B,
            const float* __restrict__ bias, void* __restrict__ CoutV)
{
    extern __shared__ __align__(16) __half sh[];
    const uint32_t sb = (uint32_t)__cvta_generic_to_shared(sh);

    const int tid  = threadIdx.x;
    const int lane = tid & 31;
    const int warp = tid >> 5;
    const int wm = (warp & 1) * 64;
    const int wn = (warp >> 1) * 32;
    const int g  = lane >> 2;
    const int q  = lane & 3;

    const int m0 = blockIdx.y * TBM;
    const int n0 = blockIdx.x * TBN;

    const int lrow = tid >> 1;
    const int lh   = (tid & 1) * 16;
    const long a_base = (GATHER_A ? (long)row_offset(m0 + lrow)
                                  : (long)(m0 + lrow) * KDIM) + lh;
    const long b_base = (long)(n0 + lrow) * KDIM + lh;
    const uint32_t sts_a = sb + (uint32_t)(lrow * PADH + lh) * 2;
    const uint32_t sts_b = sts_a + STG_H * 2;

    const uint32_t aAddr = sb + (uint32_t)((wm + g) * PADH) * 2 + (uint32_t)(q * 8);
    const uint32_t bAddr = sb + (uint32_t)STG_H * 2
                         + (uint32_t)((wn + g) * PADH) * 2 + (uint32_t)(q * 8);

    float acc[4][4][4];
    #pragma unroll
    for (int i = 0; i < 4; i++)
        #pragma unroll
        for (int j = 0; j < 4; j++)
            #pragma unroll
            for (int c = 0; c < 4; c++) acc[i][j][c] = 0.f;

    auto stage = [&](int s, int k0) {
        const __half* ag = A + a_base + k0;
        const __half* bg = B + b_base + k0;
        const uint32_t so = (uint32_t)(s * STG_B);
        cpa16(sts_a + so,      ag);
        cpa16(sts_a + so + 16, ag + 8);
        cpa16(sts_b + so,      bg);
        cpa16(sts_b + so + 16, bg + 8);
        asm volatile("cp.async.commit_group;");
    };

    stage(0, 0);
    stage(1, 32);
    stage(2, 64);

    const int NT = KDIM / 32;   // 8
    #pragma unroll 1
    for (int t = 0; t < NT; ++t) {
        asm volatile("cp.async.wait_group 2;");
        __syncthreads();
        if (t + 3 < NT) stage((t + 3) & 3, (t + 3) * 32);

        const uint32_t so = (uint32_t)((t & 3) * STG_B);
        const uint32_t ab = aAddr + so;
        const uint32_t bb = bAddr + so;
        #pragma unroll
        for (int kk = 0; kk < 2; kk++) {
            const uint32_t ko = (uint32_t)(kk * 32);
            uint32_t af[4][4];
            #pragma unroll
            for (int mt = 0; mt < 4; mt++) {
                uint2 lo = lds64(ab + (uint32_t)(mt * 16 * PADH * 2) + ko);
                uint2 hi = lds64(ab + (uint32_t)((mt * 16 + 8) * PADH * 2) + ko);
                af[mt][0] = lo.x; af[mt][1] = hi.x;
                af[mt][2] = lo.y; af[mt][3] = hi.y;
            }
            #pragma unroll
            for (int nt = 0; nt < 4; nt++) {
                uint2 b2 = lds64(bb + (uint32_t)(nt * 8 * PADH * 2) + ko);
                #pragma unroll
                for (int mt = 0; mt < 4; mt++)
                    mma16816(acc[mt][nt], af[mt][0], af[mt][1], af[mt][2],
                             af[mt][3], b2.x, b2.y);
            }
        }
        __syncthreads();
    }

    #pragma unroll
    for (int mt = 0; mt < 4; mt++) {
        #pragma unroll
        for (int ri = 0; ri < 2; ri++) {
            const int m = m0 + wm + mt * 16 + g + ri * 8;
            const long ob = SCATTER_OUT ? (long)row_offset(m) : (long)m * NTOT;
            #pragma unroll
            for (int nt = 0; nt < 4; nt++) {
                const int col = n0 + wn + nt * 8 + 2 * q;
                float vx = acc[mt][nt][ri * 2 + 0];
                float vy = acc[mt][nt][ri * 2 + 1];
                if (OUT_HALF) {
                    __half2 hv = __floats2half2_rn(vx, vy);
                    *(__half2*)((__half*)CoutV + ob + col) = hv;
                } else {
                    if (SCATTER_OUT) {
                        vx += bias[col];
                        vy += bias[col + 1];
                    }
                    float2 v; v.x = vx; v.y = vy;
                    *(float2*)((float*)CoutV + ob + col) = v;
                }
            }
        }
    }
}

// ---------------------------------------------------------------------------
// Per-token head-mixing attention: fp16-resident smem (half2), fp32 compute,
// fp16 k16-interleaved output. 128 thr = 16 tokens x 8 heads.
// Row stride 388 half2 (776 halves): tokens in a warp hit disjoint banks.
// ---------------------------------------------------------------------------
#define ATT_TOK 16
#define ATT_THREADS 128

__global__ __launch_bounds__(ATT_THREADS)
void attn_kernel(const __half* __restrict__ qkv, __half* __restrict__ att)
{
    __shared__ __half2 rows[ATT_TOK][388];   // 768 halves + 8 pad

    const int tid  = threadIdx.x;
    const int tok0 = blockIdx.x * ATT_TOK;

    // stage: 16 rows x 96 uint4 (8 halves each)
    for (int i = tid; i < ATT_TOK * 96; i += ATT_THREADS) {
        int t = i / 96, c = i - t * 96;
        uint4 u = *(const uint4*)(qkv + (size_t)(tok0 + t) * QKV_N + c * 8);
        *(uint4*)&rows[t][c * 4] = u;
    }
    __syncthreads();

    const int t = tid >> 3;
    const int h = tid & 7;
    const __half2* row = rows[t];

    // q: 16 half2 -> float2
    float2 qf[16];
    #pragma unroll
    for (int i = 0; i < 16; i++) qf[i] = __half22float2(row[h * 16 + i]);

    const float scale = 0.17677669529663687f;
    float a[8];
    #pragma unroll
    for (int e = 0; e < 8; e++) {
        const __half2* kp = row + 128 + e * 16;
        float acc = 0.f;
        #pragma unroll
        for (int i = 0; i < 16; i++) {
            float2 kf = __half22float2(kp[i]);
            acc += qf[i].x * kf.x + qf[i].y * kf.y;
        }
        a[e] = acc * scale;
    }

    float mx = a[0];
    #pragma unroll
    for (int e = 1; e < 8; e++) mx = fmaxf(mx, a[e]);
    float sum = 0.f;
    #pragma unroll
    for (int e = 0; e < 8; e++) { a[e] = __expf(a[e] - mx); sum += a[e]; }
    float inv = 1.f / sum;
    #pragma unroll
    for (int e = 0; e < 8; e++) a[e] *= inv;

    float2 o2[16];
    #pragma unroll
    for (int i = 0; i < 16; i++) { o2[i].x = 0.f; o2[i].y = 0.f; }
    #pragma unroll
    for (int e = 0; e < 8; e++) {
        const float ae = a[e];
        const __half2* vp = row + 256 + e * 16;
        #pragma unroll
        for (int i = 0; i < 16; i++) {
            float2 vf = __half22float2(vp[i]);
            o2[i].x += ae * vf.x;
            o2[i].y += ae * vf.y;
        }
    }

    // fp16 + k16 interleave, layout w*12544 + h*1568 + s*32 + d
    const int n = tok0 + t;
    const int w = n / 49;
    const int s = n - w * 49;
    __half* op = att + (size_t)w * 12544 + h * 1568 + s * 32;

    __half tmp[32];
    #pragma unroll
    for (int d = 0; d < 32; d++) {
        float val = (d & 1) ? o2[d >> 1].y : o2[d >> 1].x;
        int g16 = d >> 4, r = d & 15;
        tmp[g16 * 16 + kslot(r)] = __float2half_rn(val);
    }
    uint4* ov = (uint4*)op;
    ov[0] = *(uint4*)&tmp[0];
    ov[1] = *(uint4*)&tmp[8];
    ov[2] = *(uint4*)&tmp[16];
    ov[3] = *(uint4*)&tmp[24];
}

// ---------------------------------------------------------------------------
extern "C" void kernel_launch(void* const* d_in, const int* in_sizes, int n_in,
                              void* d_out, int out_size)
{
    (void)in_sizes; (void)n_in; (void)out_size;
    const float* x      = (const float*)d_in[0];
    const float* w_qkv  = (const float*)d_in[1];
    const float* w_proj = (const float*)d_in[2];
    const float* b_proj = (const float*)d_in[3];
    float* out = (float*)d_out;

    void *qkv_p, *att_p, *x16_p, *wq16_p, *wp16_p;
    cudaGetSymbolAddress(&qkv_p, g_qkv16);
    cudaGetSymbolAddress(&att_p, g_att16);
    cudaGetSymbolAddress(&x16_p, g_x16);
    cudaGetSymbolAddress(&wq16_p, g_wqkv16);
    cudaGetSymbolAddress(&wp16_p, g_wproj16);
    __half* qkv  = (__half*)qkv_p;
    __half* att  = (__half*)att_p;
    __half* x16  = (__half*)x16_p;
    __half* wq16 = (__half*)wq16_p;
    __half* wp16 = (__half*)wp16_p;

    static bool attr_done = false;
    if (!attr_done) {
        cudaFuncSetAttribute((const void*)gemm_h<QKV_N, true, false, true>,
                             cudaFuncAttributeMaxDynamicSharedMemorySize, SMEMB);
        cudaFuncSetAttribute((const void*)gemm_h<KDIM, false, true, false>,
                             cudaFuncAttributeMaxDynamicSharedMemorySize, SMEMB);
        attr_done = true;
    }

    // 0) fp32 -> fp16 (k16-interleaved) conversions
    {
        int ngx = 32 * 56 * 56 * 256 / 16;
        cvt16<<<(ngx + 255) / 256, 256>>>(x, x16, ngx);
        int ngq = QKV_N * KDIM / 16;
        cvt16<<<(ngq + 255) / 256, 256>>>(w_qkv, wq16, ngq);
        int ngp = KDIM * KDIM / 16;
        cvt16<<<(ngp + 255) / 256, 256>>>(w_proj, wp16, ngp);
    }
    // 1) QKV projection (gathered A), fp16 output
    {
        dim3 grid(QKV_N / TBN, M_TOK / TBM);   // (6, 784)
        gemm_h<QKV_N, true, false, true><<<grid, 256, SMEMB>>>(x16, wq16, nullptr, qkv);
    }
    // 2) attention (fp16 in/out)
    {
        attn_kernel<<<M_TOK / ATT_TOK, ATT_THREADS>>>(qkv, att);
    }
    // 3) output projection + bias + scatter (fp32 out)
    {
        dim3 grid(KDIM / TBN, M_TOK / TBM);    // (2, 784)
        gemm_h<KDIM, false, true, false><<<grid, 256, SMEMB>>>(att, wp16, b_proj, out);
    }
}

// round 15
// speedup vs baseline: 1.2774x; 1.0450x over previous
#include <cuda_runtime.h>
#include <cuda_fp16.h>
#include <cstdint>

// ---------------------------------------------------------------------------
// WindowAttention (reference semantics):
//   qkv = window_gather(x) @ w_qkv^T          [100352 x 768]
//   per token: A[h,e] = softmax_e(q_h . k_e / sqrt(32));  o_h = sum_e A[h,e] v_e
//   att layout per window: h*1568 + s*32 + d  (swapaxes(1,2) flatten)
//   out = att @ w_proj^T + b, window-scattered back to (32,56,56,256)
//
// fp16 m16n8k16 GEMMs (4-stage cp.async ring, pad-48 rows, k16-interleaved
// operands, frag pair = 1 LDS.64). Single __syncthreads per K-chunk; both
// k16 steps' fragments hoisted (MLP 24). qkv fp16; attn fp16-resident.
// ---------------------------------------------------------------------------

#define M_TOK 100352
#define KDIM  256
#define QKV_N 768

__device__ __half g_qkv16[(size_t)M_TOK * QKV_N];          // fp16 plain
__device__ __half g_att16[(size_t)M_TOK * KDIM];           // fp16 interleaved
__device__ __half g_x16[(size_t)32 * 56 * 56 * 256];       // fp16 interleaved
__device__ __half g_wqkv16[(size_t)QKV_N * KDIM];
__device__ __half g_wproj16[(size_t)KDIM * KDIM];

__device__ __host__ __forceinline__ int kslot(int r) {
    return (r & 1) | (((r >> 3) & 1) << 1) | (((r >> 1) & 3) << 2);
}

__device__ __forceinline__ int row_offset(int n) {
    int w  = n / 49;
    int s  = n - w * 49;
    int b  = w >> 6;
    int wh = (w >> 3) & 7;
    int ww = w & 7;
    int r  = s / 7;
    int cc = s - r * 7;
    int hh = wh * 7 + r;
    int wc = ww * 7 + cc;
    return ((b * 56 + hh) * 56 + wc) * 256;
}

// ---------------- fp32 -> fp16 with k16 interleave -------------------------
__global__ void cvt16(const float* __restrict__ in, __half* __restrict__ out,
                      int ngroups)
{
    int i = blockIdx.x * blockDim.x + threadIdx.x;
    if (i >= ngroups) return;
    const float4* p = (const float4*)(in + (size_t)i * 16);
    float f[16];
    *(float4*)&f[0]  = p[0];
    *(float4*)&f[4]  = p[1];
    *(float4*)&f[8]  = p[2];
    *(float4*)&f[12] = p[3];
    __half t[16];
    #pragma unroll
    for (int r = 0; r < 16; r++) t[kslot(r)] = __float2half_rn(f[r]);
    uint4* o = (uint4*)(out + (size_t)i * 16);
    o[0] = *(uint4*)&t[0];
    o[1] = *(uint4*)&t[8];
}

// ---------------------------------------------------------------------------
// fp16 TC GEMM: C[M x NTOT] = A[M x 256] * B[NTOT x 256]^T
// ---------------------------------------------------------------------------
#define TBM 128
#define TBN 128
#define PADH 48                        // halves per chunk-row (96 B)
#define STG_H (128 * PADH)
#define STG_B (2 * STG_H * 2)          // 24576
#define SMEMB (4 * STG_B)              // 98304

__device__ __forceinline__ void cpa16(uint32_t s, const void* g) {
    asm volatile("cp.async.cg.shared.global [%0], [%1], 16;" :: "r"(s), "l"(g));
}
__device__ __forceinline__ uint2 lds64(uint32_t a) {
    uint2 r;
    asm volatile("ld.shared.v2.b32 {%0,%1}, [%2];" : "=r"(r.x), "=r"(r.y) : "r"(a));
    return r;
}
__device__ __forceinline__ void mma16816(float c[4], uint32_t a0, uint32_t a1,
                                         uint32_t a2, uint32_t a3,
                                         uint32_t b0, uint32_t b1) {
    asm volatile(
        "mma.sync.aligned.m16n8k16.row.col.f32.f16.f16.f32 "
        "{%0,%1,%2,%3}, {%4,%5,%6,%7}, {%8,%9}, {%0,%1,%2,%3};"
        : "+f"(c[0]), "+f"(c[1]), "+f"(c[2]), "+f"(c[3])
        : "r"(a0), "r"(a1), "r"(a2), "r"(a3), "r"(b0), "r"(b1));
}

template<int NTOT, bool GATHER_A, bool SCATTER_OUT, bool OUT_HALF>
__global__ __launch_bounds__(256, 2)
void gemm_h(const __half* __restrict__ A, const __half* __restrict__ B,
            const float* __restrict__ bias, void* __restrict__ CoutV)
{
    extern __shared__ __align__(16) __half sh[];
    const uint32_t sb = (uint32_t)__cvta_generic_to_shared(sh);

    const int tid  = threadIdx.x;
    const int lane = tid & 31;
    const int warp = tid >> 5;
    const int wm = (warp & 1) * 64;
    const int wn = (warp >> 1) * 32;
    const int g  = lane >> 2;
    const int q  = lane & 3;

    const int m0 = blockIdx.y * TBM;
    const int n0 = blockIdx.x * TBN;

    const int lrow = tid >> 1;
    const int lh   = (tid & 1) * 16;
    const long a_base = (GATHER_A ? (long)row_offset(m0 + lrow)
                                  : (long)(m0 + lrow) * KDIM) + lh;
    const long b_base = (long)(n0 + lrow) * KDIM + lh;
    const uint32_t sts_a = sb + (uint32_t)(lrow * PADH + lh) * 2;
    const uint32_t sts_b = sts_a + STG_H * 2;

    const uint32_t aAddr = sb + (uint32_t)((wm + g) * PADH) * 2 + (uint32_t)(q * 8);
    const uint32_t bAddr = sb + (uint32_t)STG_H * 2
                         + (uint32_t)((wn + g) * PADH) * 2 + (uint32_t)(q * 8);

    float acc[4][4][4];
    #pragma unroll
    for (int i = 0; i < 4; i++)
        #pragma unroll
        for (int j = 0; j < 4; j++)
            #pragma unroll
            for (int c = 0; c < 4; c++) acc[i][j][c] = 0.f;

    auto stage = [&](int s, int k0) {
        const __half* ag = A + a_base + k0;
        const __half* bg = B + b_base + k0;
        const uint32_t so = (uint32_t)(s * STG_B);
        cpa16(sts_a + so,      ag);
        cpa16(sts_a + so + 16, ag + 8);
        cpa16(sts_b + so,      bg);
        cpa16(sts_b + so + 16, bg + 8);
        asm volatile("cp.async.commit_group;");
    };

    stage(0, 0);
    stage(1, 32);
    stage(2, 64);

    const int NT = KDIM / 32;   // 8
    #pragma unroll 1
    for (int t = 0; t < NT; ++t) {
        asm volatile("cp.async.wait_group 2;");
        __syncthreads();
        if (t + 3 < NT) stage((t + 3) & 3, (t + 3) * 32);

        const uint32_t so = (uint32_t)((t & 3) * STG_B);
        const uint32_t ab = aAddr + so;
        const uint32_t bb = bAddr + so;

        // hoist BOTH k16 steps' fragment loads (24 LDS.64, MLP 24)
        uint32_t af[2][4][4], bf[2][4][2];
        #pragma unroll
        for (int kk = 0; kk < 2; kk++) {
            const uint32_t ko = (uint32_t)(kk * 32);
            #pragma unroll
            for (int mt = 0; mt < 4; mt++) {
                uint2 lo = lds64(ab + (uint32_t)(mt * 16 * PADH * 2) + ko);
                uint2 hi = lds64(ab + (uint32_t)((mt * 16 + 8) * PADH * 2) + ko);
                af[kk][mt][0] = lo.x; af[kk][mt][1] = hi.x;
                af[kk][mt][2] = lo.y; af[kk][mt][3] = hi.y;
            }
            #pragma unroll
            for (int nt = 0; nt < 4; nt++) {
                uint2 b2 = lds64(bb + (uint32_t)(nt * 8 * PADH * 2) + ko);
                bf[kk][nt][0] = b2.x; bf[kk][nt][1] = b2.y;
            }
        }
        #pragma unroll
        for (int kk = 0; kk < 2; kk++)
            #pragma unroll
            for (int nt = 0; nt < 4; nt++)
                #pragma unroll
                for (int mt = 0; mt < 4; mt++)
                    mma16816(acc[mt][nt], af[kk][mt][0], af[kk][mt][1],
                             af[kk][mt][2], af[kk][mt][3],
                             bf[kk][nt][0], bf[kk][nt][1]);
        // no trailing sync: next chunk's top sync protects buffer reuse
    }

    #pragma unroll
    for (int mt = 0; mt < 4; mt++) {
        #pragma unroll
        for (int ri = 0; ri < 2; ri++) {
            const int m = m0 + wm + mt * 16 + g + ri * 8;
            const long ob = SCATTER_OUT ? (long)row_offset(m) : (long)m * NTOT;
            #pragma unroll
            for (int nt = 0; nt < 4; nt++) {
                const int col = n0 + wn + nt * 8 + 2 * q;
                float vx = acc[mt][nt][ri * 2 + 0];
                float vy = acc[mt][nt][ri * 2 + 1];
                if (OUT_HALF) {
                    __half2 hv = __floats2half2_rn(vx, vy);
                    *(__half2*)((__half*)CoutV + ob + col) = hv;
                } else {
                    if (SCATTER_OUT) {
                        vx += bias[col];
                        vy += bias[col + 1];
                    }
                    float2 v; v.x = vx; v.y = vy;
                    *(float2*)((float*)CoutV + ob + col) = v;
                }
            }
        }
    }
}

// ---------------------------------------------------------------------------
// Per-token head-mixing attention: fp16-resident smem (half2), fp32 compute,
// fp16 k16-interleaved output. 128 thr = 16 tokens x 8 heads.
// ---------------------------------------------------------------------------
#define ATT_TOK 16
#define ATT_THREADS 128

__global__ __launch_bounds__(ATT_THREADS)
void attn_kernel(const __half* __restrict__ qkv, __half* __restrict__ att)
{
    __shared__ __half2 rows[ATT_TOK][388];   // 768 halves + 8 pad

    const int tid  = threadIdx.x;
    const int tok0 = blockIdx.x * ATT_TOK;

    for (int i = tid; i < ATT_TOK * 96; i += ATT_THREADS) {
        int t = i / 96, c = i - t * 96;
        uint4 u = *(const uint4*)(qkv + (size_t)(tok0 + t) * QKV_N + c * 8);
        *(uint4*)&rows[t][c * 4] = u;
    }
    __syncthreads();

    const int t = tid >> 3;
    const int h = tid & 7;
    const __half2* row = rows[t];

    float2 qf[16];
    #pragma unroll
    for (int i = 0; i < 16; i++) qf[i] = __half22float2(row[h * 16 + i]);

    const float scale = 0.17677669529663687f;
    float a[8];
    #pragma unroll
    for (int e = 0; e < 8; e++) {
        const __half2* kp = row + 128 + e * 16;
        float acc = 0.f;
        #pragma unroll
        for (int i = 0; i < 16; i++) {
            float2 kf = __half22float2(kp[i]);
            acc += qf[i].x * kf.x + qf[i].y * kf.y;
        }
        a[e] = acc * scale;
    }

    float mx = a[0];
    #pragma unroll
    for (int e = 1; e < 8; e++) mx = fmaxf(mx, a[e]);
    float sum = 0.f;
    #pragma unroll
    for (int e = 0; e < 8; e++) { a[e] = __expf(a[e] - mx); sum += a[e]; }
    float inv = 1.f / sum;
    #pragma unroll
    for (int e = 0; e < 8; e++) a[e] *= inv;

    float2 o2[16];
    #pragma unroll
    for (int i = 0; i < 16; i++) { o2[i].x = 0.f; o2[i].y = 0.f; }
    #pragma unroll
    for (int e = 0; e < 8; e++) {
        const float ae = a[e];
        const __half2* vp = row + 256 + e * 16;
        #pragma unroll
        for (int i = 0; i < 16; i++) {
            float2 vf = __half22float2(vp[i]);
            o2[i].x += ae * vf.x;
            o2[i].y += ae * vf.y;
        }
    }

    const int n = tok0 + t;
    const int w = n / 49;
    const int s = n - w * 49;
    __half* op = att + (size_t)w * 12544 + h * 1568 + s * 32;

    __half tmp[32];
    #pragma unroll
    for (int d = 0; d < 32; d++) {
        float val = (d & 1) ? o2[d >> 1].y : o2[d >> 1].x;
        int g16 = d >> 4, r = d & 15;
        tmp[g16 * 16 + kslot(r)] = __float2half_rn(val);
    }
    uint4* ov = (uint4*)op;
    ov[0] = *(uint4*)&tmp[0];
    ov[1] = *(uint4*)&tmp[8];
    ov[2] = *(uint4*)&tmp[16];
    ov[3] = *(uint4*)&tmp[24];
}

// ---------------------------------------------------------------------------
extern "C" void kernel_launch(void* const* d_in, const int* in_sizes, int n_in,
                              void* d_out, int out_size)
{
    (void)in_sizes; (void)n_in; (void)out_size;
    const float* x      = (const float*)d_in[0];
    const float* w_qkv  = (const float*)d_in[1];
    const float* w_proj = (const float*)d_in[2];
    const float* b_proj = (const float*)d_in[3];
    float* out = (float*)d_out;

    void *qkv_p, *att_p, *x16_p, *wq16_p, *wp16_p;
    cudaGetSymbolAddress(&qkv_p, g_qkv16);
    cudaGetSymbolAddress(&att_p, g_att16);
    cudaGetSymbolAddress(&x16_p, g_x16);
    cudaGetSymbolAddress(&wq16_p, g_wqkv16);
    cudaGetSymbolAddress(&wp16_p, g_wproj16);
    __half* qkv  = (__half*)qkv_p;
    __half* att  = (__half*)att_p;
    __half* x16  = (__half*)x16_p;
    __half* wq16 = (__half*)wq16_p;
    __half* wp16 = (__half*)wp16_p;

    static bool attr_done = false;
    if (!attr_done) {
        cudaFuncSetAttribute((const void*)gemm_h<QKV_N, true, false, true>,
                             cudaFuncAttributeMaxDynamicSharedMemorySize, SMEMB);
        cudaFuncSetAttribute((const void*)gemm_h<KDIM, false, true, false>,
                             cudaFuncAttributeMaxDynamicSharedMemorySize, SMEMB);
        attr_done = true;
    }

    // 0) fp32 -> fp16 (k16-interleaved) conversions
    {
        int ngx = 32 * 56 * 56 * 256 / 16;
        cvt16<<<(ngx + 255) / 256, 256>>>(x, x16, ngx);
        int ngq = QKV_N * KDIM / 16;
        cvt16<<<(ngq + 255) / 256, 256>>>(w_qkv, wq16, ngq);
        int ngp = KDIM * KDIM / 16;
        cvt16<<<(ngp + 255) / 256, 256>>>(w_proj, wp16, ngp);
    }
    // 1) QKV projection (gathered A), fp16 output
    {
        dim3 grid(QKV_N / TBN, M_TOK / TBM);   // (6, 784)
        gemm_h<QKV_N, true, false, true><<<grid, 256, SMEMB>>>(x16, wq16, nullptr, qkv);
    }
    // 2) attention (fp16 in/out)
    {
        attn_kernel<<<M_TOK / ATT_TOK, ATT_THREADS>>>(qkv, att);
    }
    // 3) output projection + bias + scatter (fp32 out)
    {
        dim3 grid(KDIM / TBN, M_TOK / TBM);    // (2, 784)
        gemm_h<KDIM, false, true, false><<<grid, 256, SMEMB>>>(att, wp16, b_proj, out);
    }
}

// round 16
// speedup vs baseline: 1.3394x; 1.0485x over previous
#include <cuda_runtime.h>
#include <cuda_fp16.h>
#include <cstdint>

// ---------------------------------------------------------------------------
// WindowAttention (reference semantics):
//   qkv = window_gather(x) @ w_qkv^T          [100352 x 768]
//   per token: A[h,e] = softmax_e(q_h . k_e / sqrt(32));  o_h = sum_e A[h,e] v_e
//   att layout per window: h*1568 + s*32 + d  (swapaxes(1,2) flatten)
//   out = att @ w_proj^T + b, window-scattered back to (32,56,56,256)
//
// fp16 m16n8k16 GEMMs (4-stage cp.async ring, pad-48 rows, k16-interleaved
// operands, frag pair = 1 LDS.64, single sync/chunk, hoisted fragments).
// Attention: fp16-resident smem, LDS.128 reads, half2 math (fp32 softmax).
// ---------------------------------------------------------------------------

#define M_TOK 100352
#define KDIM  256
#define QKV_N 768

__device__ __half g_qkv16[(size_t)M_TOK * QKV_N];          // fp16 plain
__device__ __half g_att16[(size_t)M_TOK * KDIM];           // fp16 interleaved
__device__ __half g_x16[(size_t)32 * 56 * 56 * 256];       // fp16 interleaved
__device__ __half g_wqkv16[(size_t)QKV_N * KDIM];
__device__ __half g_wproj16[(size_t)KDIM * KDIM];

__device__ __host__ __forceinline__ int kslot(int r) {
    return (r & 1) | (((r >> 3) & 1) << 1) | (((r >> 1) & 3) << 2);
}

__device__ __forceinline__ int row_offset(int n) {
    int w  = n / 49;
    int s  = n - w * 49;
    int b  = w >> 6;
    int wh = (w >> 3) & 7;
    int ww = w & 7;
    int r  = s / 7;
    int cc = s - r * 7;
    int hh = wh * 7 + r;
    int wc = ww * 7 + cc;
    return ((b * 56 + hh) * 56 + wc) * 256;
}

// ---------------- fp32 -> fp16 with k16 interleave -------------------------
__global__ void cvt16(const float* __restrict__ in, __half* __restrict__ out,
                      int ngroups)
{
    int i = blockIdx.x * blockDim.x + threadIdx.x;
    if (i >= ngroups) return;
    const float4* p = (const float4*)(in + (size_t)i * 16);
    float f[16];
    *(float4*)&f[0]  = p[0];
    *(float4*)&f[4]  = p[1];
    *(float4*)&f[8]  = p[2];
    *(float4*)&f[12] = p[3];
    __half t[16];
    #pragma unroll
    for (int r = 0; r < 16; r++) t[kslot(r)] = __float2half_rn(f[r]);
    uint4* o = (uint4*)(out + (size_t)i * 16);
    o[0] = *(uint4*)&t[0];
    o[1] = *(uint4*)&t[8];
}

// ---------------------------------------------------------------------------
// fp16 TC GEMM: C[M x NTOT] = A[M x 256] * B[NTOT x 256]^T   (R15 structure)
// ---------------------------------------------------------------------------
#define TBM 128
#define TBN 128
#define PADH 48
#define STG_H (128 * PADH)
#define STG_B (2 * STG_H * 2)          // 24576
#define SMEMB (4 * STG_B)              // 98304

__device__ __forceinline__ void cpa16(uint32_t s, const void* g) {
    asm volatile("cp.async.cg.shared.global [%0], [%1], 16;" :: "r"(s), "l"(g));
}
__device__ __forceinline__ uint2 lds64(uint32_t a) {
    uint2 r;
    asm volatile("ld.shared.v2.b32 {%0,%1}, [%2];" : "=r"(r.x), "=r"(r.y) : "r"(a));
    return r;
}
__device__ __forceinline__ void mma16816(float c[4], uint32_t a0, uint32_t a1,
                                         uint32_t a2, uint32_t a3,
                                         uint32_t b0, uint32_t b1) {
    asm volatile(
        "mma.sync.aligned.m16n8k16.row.col.f32.f16.f16.f32 "
        "{%0,%1,%2,%3}, {%4,%5,%6,%7}, {%8,%9}, {%0,%1,%2,%3};"
        : "+f"(c[0]), "+f"(c[1]), "+f"(c[2]), "+f"(c[3])
        : "r"(a0), "r"(a1), "r"(a2), "r"(a3), "r"(b0), "r"(b1));
}

template<int NTOT, bool GATHER_A, bool SCATTER_OUT, bool OUT_HALF>
__global__ __launch_bounds__(256, 2)
void gemm_h(const __half* __restrict__ A, const __half* __restrict__ B,
            const float* __restrict__ bias, void* __restrict__ CoutV)
{
    extern __shared__ __align__(16) __half sh[];
    const uint32_t sb = (uint32_t)__cvta_generic_to_shared(sh);

    const int tid  = threadIdx.x;
    const int lane = tid & 31;
    const int warp = tid >> 5;
    const int wm = (warp & 1) * 64;
    const int wn = (warp >> 1) * 32;
    const int g  = lane >> 2;
    const int q  = lane & 3;

    const int m0 = blockIdx.y * TBM;
    const int n0 = blockIdx.x * TBN;

    const int lrow = tid >> 1;
    const int lh   = (tid & 1) * 16;
    const long a_base = (GATHER_A ? (long)row_offset(m0 + lrow)
                                  : (long)(m0 + lrow) * KDIM) + lh;
    const long b_base = (long)(n0 + lrow) * KDIM + lh;
    const uint32_t sts_a = sb + (uint32_t)(lrow * PADH + lh) * 2;
    const uint32_t sts_b = sts_a + STG_H * 2;

    const uint32_t aAddr = sb + (uint32_t)((wm + g) * PADH) * 2 + (uint32_t)(q * 8);
    const uint32_t bAddr = sb + (uint32_t)STG_H * 2
                         + (uint32_t)((wn + g) * PADH) * 2 + (uint32_t)(q * 8);

    float acc[4][4][4];
    #pragma unroll
    for (int i = 0; i < 4; i++)
        #pragma unroll
        for (int j = 0; j < 4; j++)
            #pragma unroll
            for (int c = 0; c < 4; c++) acc[i][j][c] = 0.f;

    auto stage = [&](int s, int k0) {
        const __half* ag = A + a_base + k0;
        const __half* bg = B + b_base + k0;
        const uint32_t so = (uint32_t)(s * STG_B);
        cpa16(sts_a + so,      ag);
        cpa16(sts_a + so + 16, ag + 8);
        cpa16(sts_b + so,      bg);
        cpa16(sts_b + so + 16, bg + 8);
        asm volatile("cp.async.commit_group;");
    };

    stage(0, 0);
    stage(1, 32);
    stage(2, 64);

    const int NT = KDIM / 32;   // 8
    #pragma unroll 1
    for (int t = 0; t < NT; ++t) {
        asm volatile("cp.async.wait_group 2;");
        __syncthreads();
        if (t + 3 < NT) stage((t + 3) & 3, (t + 3) * 32);

        const uint32_t so = (uint32_t)((t & 3) * STG_B);
        const uint32_t ab = aAddr + so;
        const uint32_t bb = bAddr + so;

        uint32_t af[2][4][4], bf[2][4][2];
        #pragma unroll
        for (int kk = 0; kk < 2; kk++) {
            const uint32_t ko = (uint32_t)(kk * 32);
            #pragma unroll
            for (int mt = 0; mt < 4; mt++) {
                uint2 lo = lds64(ab + (uint32_t)(mt * 16 * PADH * 2) + ko);
                uint2 hi = lds64(ab + (uint32_t)((mt * 16 + 8) * PADH * 2) + ko);
                af[kk][mt][0] = lo.x; af[kk][mt][1] = hi.x;
                af[kk][mt][2] = lo.y; af[kk][mt][3] = hi.y;
            }
            #pragma unroll
            for (int nt = 0; nt < 4; nt++) {
                uint2 b2 = lds64(bb + (uint32_t)(nt * 8 * PADH * 2) + ko);
                bf[kk][nt][0] = b2.x; bf[kk][nt][1] = b2.y;
            }
        }
        #pragma unroll
        for (int kk = 0; kk < 2; kk++)
            #pragma unroll
            for (int nt = 0; nt < 4; nt++)
                #pragma unroll
                for (int mt = 0; mt < 4; mt++)
                    mma16816(acc[mt][nt], af[kk][mt][0], af[kk][mt][1],
                             af[kk][mt][2], af[kk][mt][3],
                             bf[kk][nt][0], bf[kk][nt][1]);
    }

    #pragma unroll
    for (int mt = 0; mt < 4; mt++) {
        #pragma unroll
        for (int ri = 0; ri < 2; ri++) {
            const int m = m0 + wm + mt * 16 + g + ri * 8;
            const long ob = SCATTER_OUT ? (long)row_offset(m) : (long)m * NTOT;
            #pragma unroll
            for (int nt = 0; nt < 4; nt++) {
                const int col = n0 + wn + nt * 8 + 2 * q;
                float vx = acc[mt][nt][ri * 2 + 0];
                float vy = acc[mt][nt][ri * 2 + 1];
                if (OUT_HALF) {
                    __half2 hv = __floats2half2_rn(vx, vy);
                    *(__half2*)((__half*)CoutV + ob + col) = hv;
                } else {
                    if (SCATTER_OUT) {
                        vx += bias[col];
                        vy += bias[col + 1];
                    }
                    float2 v; v.x = vx; v.y = vy;
                    *(float2*)((float*)CoutV + ob + col) = v;
                }
            }
        }
    }
}

// ---------------------------------------------------------------------------
// Per-token head-mixing attention: fp16-resident smem, LDS.128 reads,
// half2 math (fp32 softmax). 128 thr = 16 tokens x 8 heads.
// ---------------------------------------------------------------------------
#define ATT_TOK 16
#define ATT_THREADS 128

__global__ __launch_bounds__(ATT_THREADS)
void attn_kernel(const __half* __restrict__ qkv, __half* __restrict__ att)
{
    __shared__ __half2 rows[ATT_TOK][388];   // 768 halves + 8 pad; 16B-aligned rows

    const int tid  = threadIdx.x;
    const int tok0 = blockIdx.x * ATT_TOK;

    for (int i = tid; i < ATT_TOK * 96; i += ATT_THREADS) {
        int t = i / 96, c = i - t * 96;
        uint4 u = *(const uint4*)(qkv + (size_t)(tok0 + t) * QKV_N + c * 8);
        *(uint4*)&rows[t][c * 4] = u;
    }
    __syncthreads();

    const int t = tid >> 3;
    const int h = tid & 7;
    const __half2* row = rows[t];

    // q: 4 uint4 = 16 half2
    __half2 qh[16];
    #pragma unroll
    for (int j = 0; j < 4; j++)
        *(uint4*)&qh[j * 4] = *(const uint4*)&row[h * 16 + j * 4];

    // qk dot: per e, 4 HFMA2-chains of 4 (one per uint4), fp32 cross-reduce
    const float scale = 0.17677669529663687f;
    float a[8];
    #pragma unroll
    for (int e = 0; e < 8; e++) {
        const __half2* kp = row + 128 + e * 16;
        float accf = 0.f;
        #pragma unroll
        for (int j = 0; j < 4; j++) {
            __half2 kh[4];
            *(uint4*)&kh[0] = *(const uint4*)&kp[j * 4];
            __half2 s = __hmul2(qh[j * 4], kh[0]);
            s = __hfma2(qh[j * 4 + 1], kh[1], s);
            s = __hfma2(qh[j * 4 + 2], kh[2], s);
            s = __hfma2(qh[j * 4 + 3], kh[3], s);
            float2 f = __half22float2(s);
            accf += f.x + f.y;
        }
        a[e] = accf * scale;
    }

    float mx = a[0];
    #pragma unroll
    for (int e = 1; e < 8; e++) mx = fmaxf(mx, a[e]);
    float sum = 0.f;
    #pragma unroll
    for (int e = 0; e < 8; e++) { a[e] = __expf(a[e] - mx); sum += a[e]; }
    float inv = 1.f / sum;
    #pragma unroll
    for (int e = 0; e < 8; e++) a[e] *= inv;

    // v-sum in half2
    __half2 o2[16];
    #pragma unroll
    for (int i = 0; i < 16; i++) o2[i] = __float2half2_rn(0.f);
    #pragma unroll
    for (int e = 0; e < 8; e++) {
        const __half2 ae2 = __float2half2_rn(a[e]);
        const __half2* vp = row + 256 + e * 16;
        #pragma unroll
        for (int j = 0; j < 4; j++) {
            __half2 vh[4];
            *(uint4*)&vh[0] = *(const uint4*)&vp[j * 4];
            o2[j * 4 + 0] = __hfma2(ae2, vh[0], o2[j * 4 + 0]);
            o2[j * 4 + 1] = __hfma2(ae2, vh[1], o2[j * 4 + 1]);
            o2[j * 4 + 2] = __hfma2(ae2, vh[2], o2[j * 4 + 2]);
            o2[j * 4 + 3] = __hfma2(ae2, vh[3], o2[j * 4 + 3]);
        }
    }

    // fp16 + k16 interleave, layout w*12544 + h*1568 + s*32 + d
    const int n = tok0 + t;
    const int w = n / 49;
    const int s = n - w * 49;
    __half* op = att + (size_t)w * 12544 + h * 1568 + s * 32;

    __half tmp[32];
    #pragma unroll
    for (int d = 0; d < 32; d++) {
        __half val = (d & 1) ? __high2half(o2[d >> 1]) : __low2half(o2[d >> 1]);
        int g16 = d >> 4, r = d & 15;
        tmp[g16 * 16 + kslot(r)] = val;
    }
    uint4* ov = (uint4*)op;
    ov[0] = *(uint4*)&tmp[0];
    ov[1] = *(uint4*)&tmp[8];
    ov[2] = *(uint4*)&tmp[16];
    ov[3] = *(uint4*)&tmp[24];
}

// ---------------------------------------------------------------------------
extern "C" void kernel_launch(void* const* d_in, const int* in_sizes, int n_in,
                              void* d_out, int out_size)
{
    (void)in_sizes; (void)n_in; (void)out_size;
    const float* x      = (const float*)d_in[0];
    const float* w_qkv  = (const float*)d_in[1];
    const float* w_proj = (const float*)d_in[2];
    const float* b_proj = (const float*)d_in[3];
    float* out = (float*)d_out;

    void *qkv_p, *att_p, *x16_p, *wq16_p, *wp16_p;
    cudaGetSymbolAddress(&qkv_p, g_qkv16);
    cudaGetSymbolAddress(&att_p, g_att16);
    cudaGetSymbolAddress(&x16_p, g_x16);
    cudaGetSymbolAddress(&wq16_p, g_wqkv16);
    cudaGetSymbolAddress(&wp16_p, g_wproj16);
    __half* qkv  = (__half*)qkv_p;
    __half* att  = (__half*)att_p;
    __half* x16  = (__half*)x16_p;
    __half* wq16 = (__half*)wq16_p;
    __half* wp16 = (__half*)wp16_p;

    static bool attr_done = false;
    if (!attr_done) {
        cudaFuncSetAttribute((const void*)gemm_h<QKV_N, true, false, true>,
                             cudaFuncAttributeMaxDynamicSharedMemorySize, SMEMB);
        cudaFuncSetAttribute((const void*)gemm_h<KDIM, false, true, false>,
                             cudaFuncAttributeMaxDynamicSharedMemorySize, SMEMB);
        attr_done = true;
    }

    // 0) fp32 -> fp16 (k16-interleaved) conversions
    {
        int ngx = 32 * 56 * 56 * 256 / 16;
        cvt16<<<(ngx + 255) / 256, 256>>>(x, x16, ngx);
        int ngq = QKV_N * KDIM / 16;
        cvt16<<<(ngq + 255) / 256, 256>>>(w_qkv, wq16, ngq);
        int ngp = KDIM * KDIM / 16;
        cvt16<<<(ngp + 255) / 256, 256>>>(w_proj, wp16, ngp);
    }
    // 1) QKV projection (gathered A), fp16 output
    {
        dim3 grid(QKV_N / TBN, M_TOK / TBM);   // (6, 784)
        gemm_h<QKV_N, true, false, true><<<grid, 256, SMEMB>>>(x16, wq16, nullptr, qkv);
    }
    // 2) attention (fp16 in/out)
    {
        attn_kernel<<<M_TOK / ATT_TOK, ATT_THREADS>>>(qkv, att);
    }
    // 3) output projection + bias + scatter (fp32 out)
    {
        dim3 grid(KDIM / TBN, M_TOK / TBM);    // (2, 784)
        gemm_h<KDIM, false, true, false><<<grid, 256, SMEMB>>>(att, wp16, b_proj, out);
    }
}